// round 17
// baseline (speedup 1.0000x reference)
#include <cuda_runtime.h>
#include <math.h>
#include <stdint.h>

#define NT 8192      // tokens
#define CI 256       // input channels
#define NE 8         // experts
#define NH 512       // hidden
#define CO 256       // output channels
#define NR (2*NT)    // routed rows (K=2)

// ---------------- scratch (device globals; no allocation allowed) ------------
__device__ int   g_cnt[NE];
__device__ int   g_off[NE];
__device__ int   g_list[NE * NT];
__device__ float g_wt[NR];                       // weight per entry (t*2+slot)
__device__ int   g_rowof[NR];                    // entry -> segment row (for combine)
__device__ float g_xr[(size_t)NT * CI];          // token-ordered x, tf32-rounded
__device__ float g_w1r[(size_t)NE * CI * NH];    // W1 tf32-rounded [E][K][N]
__device__ float g_w2r[(size_t)NE * NH * CO];    // W2 tf32-rounded [E][K][N]
__device__ float g_hid[(size_t)NR * NH];         // hidden (segment order), tf32-rounded
__device__ float g_tmp[(size_t)NR * CO];         // weighted expert outputs (segment order)

// ---------------- helpers ----------------------------------------------------
__device__ __forceinline__ float tf32r(float x) {
    uint32_t y;
    asm("cvt.rna.tf32.f32 %0, %1;" : "=r"(y) : "f"(x));
    return __uint_as_float(y);
}
__device__ __forceinline__ void cp16(float* dst, const float* src) {
    uint32_t d = (uint32_t)__cvta_generic_to_shared(dst);
    asm volatile("cp.async.cg.shared.global [%0], [%1], 16;" :: "r"(d), "l"(src));
}
__device__ __forceinline__ void cp_commit() {
    asm volatile("cp.async.commit_group;");
}
__device__ __forceinline__ void cp_wait1() {
    asm volatile("cp.async.wait_group 1;");
}
__device__ __forceinline__ void mma_tf32(float* d, const uint32_t* a, const uint32_t* b) {
    asm volatile("mma.sync.aligned.m16n8k8.row.col.f32.tf32.tf32.f32 "
                 "{%0,%1,%2,%3}, {%4,%5,%6,%7}, {%8,%9}, {%0,%1,%2,%3};"
                 : "+f"(d[0]), "+f"(d[1]), "+f"(d[2]), "+f"(d[3])
                 : "r"(a[0]), "r"(a[1]), "r"(a[2]), "r"(a[3]),
                   "r"(b[0]), "r"(b[1]));
}

// ---------------- routing ----------------------------------------------------
__global__ void k_zero() { if (threadIdx.x < NE) g_cnt[threadIdx.x] = 0; }

// fused: blocks [0, NT/8) gate tokens + write tf32-rounded x;
//        blocks [NT/8, ...) tf32-round W1/W2
__global__ void k_gate_roundw(const float* __restrict__ x, const float* __restrict__ Wg,
                              const float* __restrict__ bg, const float* __restrict__ eb,
                              const float* __restrict__ w1, const float* __restrict__ w2) {
    __shared__ float sWg[CI * NE];
    int tid = threadIdx.x;

    if (blockIdx.x >= NT / 8) {                    // ---- weight rounding part ----
        int i = (blockIdx.x - NT / 8) * 256 + tid; // float4 index
        const int n1 = NE * CI * NH / 4;
        const int n2 = NE * NH * CO / 4;
        if (i < n1) {
            float4 v = ((const float4*)w1)[i];
            v.x = tf32r(v.x); v.y = tf32r(v.y); v.z = tf32r(v.z); v.w = tf32r(v.w);
            ((float4*)g_w1r)[i] = v;
        } else if (i < n1 + n2) {
            int j = i - n1;
            float4 v = ((const float4*)w2)[j];
            v.x = tf32r(v.x); v.y = tf32r(v.y); v.z = tf32r(v.z); v.w = tf32r(v.w);
            ((float4*)g_w2r)[j] = v;
        }
        return;
    }

    // ---- gating part (also emits tf32-rounded x in token order) ----
    for (int i = tid; i < CI * NE; i += 256) sWg[i] = Wg[i];
    __syncthreads();
    int warp = tid >> 5, lane = tid & 31;
    int t = blockIdx.x * 8 + warp;
    const float* xr = x + (size_t)t * CI;
    float* xo = g_xr + (size_t)t * CI;
    float acc[NE];
#pragma unroll
    for (int e = 0; e < NE; ++e) acc[e] = 0.f;
#pragma unroll
    for (int j = 0; j < CI / 32; ++j) {
        int c = lane + 32 * j;
        float xv = xr[c];
        xo[c] = tf32r(xv);
        const float* wr = &sWg[c * NE];
#pragma unroll
        for (int e = 0; e < NE; ++e) acc[e] = fmaf(xv, wr[e], acc[e]);
    }
#pragma unroll
    for (int e = 0; e < NE; ++e)
#pragma unroll
        for (int off = 16; off; off >>= 1)
            acc[e] += __shfl_xor_sync(0xffffffffu, acc[e], off);
    if (lane == 0) {
        float v0 = -1e30f, v1 = -1e30f; int i0 = 0, i1 = 0;
#pragma unroll
        for (int e = 0; e < NE; ++e) {
            float v = acc[e] + bg[e] + eb[e];
            if (v > v0)      { v1 = v0; i1 = i0; v0 = v; i0 = e; }
            else if (v > v1) { v1 = v;  i1 = e; }
        }
        float p0 = 1.f / (1.f + expf(-v0));
        float p1 = 1.f / (1.f + expf(-v1));
        float s  = p0 + p1;
        g_wt[t * 2]     = p0 / s;
        g_wt[t * 2 + 1] = p1 / s;
        int p = atomicAdd(&g_cnt[i0], 1);  g_list[i0 * NT + p] = t * 2;
        p     = atomicAdd(&g_cnt[i1], 1);  g_list[i1 * NT + p] = t * 2 + 1;
    }
}

__global__ void k_sched() {
    if (threadIdx.x == 0) {
        int run = 0;
        for (int e = 0; e < NE; ++e) { g_off[e] = run; run += g_cnt[e]; }
    }
}

// entry -> segment row (needed only by k_combine)
__global__ void k_build() {
    int slot = blockIdx.x * 256 + threadIdx.x;
    if (slot >= NE * NT) return;
    int e = slot >> 13, i = slot & (NT - 1);
    if (i < g_cnt[e]) g_rowof[g_list[slot]] = g_off[e] + i;
}

// ---------------- HMMA grouped GEMM ------------------------------------------
// BM=128, BN=128, BK=32; 8 warps (2x4), warp tile 64x32 (4x4 m16n8k8)
// 2 CTAs/SM; 3-stage cp.async pipeline, single __syncthreads per k-iter.
// PH1 gathers A rows via s_tok (token index list); PH2 reads contiguous g_hid.
#define BM 128
#define BN 128
#define BK 32
#define LDA 36                       // A frag bank = (4g+tg)%32: conflict-free
#define LDB 136                      // B frag bank = (8tg+g)%32: conflict-free
#define A_ST (BM * LDA)              // 4608 floats
#define B_ST (BK * LDB)              // 4352 floats
#define STG_FL (A_ST + B_ST)         // 8960 floats per stage
#define SMEM_SZ (3 * STG_FL * 4)     // 107520 bytes -> 2 CTAs/SM (215KB <= 228KB)

template<int KD, int ND, bool PH1>
__global__ __launch_bounds__(256, 2)
void k_mma(const float* __restrict__ bias) {
    extern __shared__ float sm[];
    __shared__ int s_tok[BM];
    const int e   = blockIdx.z;
    const int cnt = g_cnt[e];
    const int m0  = blockIdx.y * BM;
    if (m0 >= cnt) return;
    const int base = g_off[e];
    const int n0   = blockIdx.x * BN;
    const int tid  = threadIdx.x;
    const int lane = tid & 31;
    const int w    = tid >> 5;
    const int wm   = w >> 2, wn = w & 3;

    const float* Bsrc = (PH1 ? g_w1r : g_w2r) + (size_t)e * KD * ND;

    // A row pointers
    const int lrA = tid >> 1, lqA = tid & 1;       // 2 threads per A row (8 fl each)
    const float* gA;
    if (PH1) {
        if (tid < BM) {
            int mm = m0 + tid; mm = mm < cnt ? mm : cnt - 1;
            s_tok[tid] = g_list[e * NT + mm] >> 1;
        }
        __syncthreads();
        gA = g_xr + (size_t)s_tok[lrA] * KD + lqA * 16;
    } else {
        int mm = m0 + lrA; mm = mm < cnt ? mm : cnt - 1;
        gA = g_hid + (size_t)(base + mm) * KD + lqA * 16;
    }

    auto load_stage = [&](int kb, int buf) {
        float* as = sm + buf * STG_FL;
        float* bs = as + A_ST;
        const int k0 = kb * BK;
        // A: 128 rows x 32 fl; each thread: 1 row, 16 fl (4 cp16)
#pragma unroll
        for (int q = 0; q < 4; ++q)
            cp16(as + lrA * LDA + lqA * 16 + q * 4, gA + k0 + q * 4);
        // B: 32 rows x 128 fl
#pragma unroll
        for (int c = 0; c < 4; ++c) {
            int idx = tid + c * 256;
            int k = idx >> 5, q = idx & 31;
            cp16(bs + k * LDB + q * 4,
                 Bsrc + (size_t)(k0 + k) * ND + n0 + q * 4);
        }
        cp_commit();
    };

    float acc[4][4][4];
#pragma unroll
    for (int mt = 0; mt < 4; ++mt)
#pragma unroll
        for (int nt = 0; nt < 4; ++nt)
#pragma unroll
            for (int j = 0; j < 4; ++j) acc[mt][nt][j] = 0.f;

    const int NK = KD / BK;
    load_stage(0, 0);
    load_stage(1, 1);
    int buf = 0, bufw = 2;                         // read / write rotors
    for (int kb = 0; kb < NK; ++kb) {
        cp_wait1();                                // stage kb arrived (kb+1 in flight)
        __syncthreads();                           // all done reading buffer bufw
        if (kb + 2 < NK) load_stage(kb + 2, bufw);
        const float* as = sm + buf * STG_FL;
        const float* bs = as + A_ST;
        const float* pA = as + (wm * 64 + (lane >> 2)) * LDA + (lane & 3);
        const float* pB = bs + (lane & 3) * LDB + wn * 32 + (lane >> 2);
#pragma unroll
        for (int ks = 0; ks < 4; ++ks) {
            uint32_t af[4][4], bf[4][2];
#pragma unroll
            for (int mt = 0; mt < 4; ++mt) {
                af[mt][0] = __float_as_uint(pA[(mt * 16)     * LDA + ks * 8]);
                af[mt][1] = __float_as_uint(pA[(mt * 16 + 8) * LDA + ks * 8]);
                af[mt][2] = __float_as_uint(pA[(mt * 16)     * LDA + ks * 8 + 4]);
                af[mt][3] = __float_as_uint(pA[(mt * 16 + 8) * LDA + ks * 8 + 4]);
            }
#pragma unroll
            for (int nt = 0; nt < 4; ++nt) {
                bf[nt][0] = __float_as_uint(pB[(ks * 8)     * LDB + nt * 8]);
                bf[nt][1] = __float_as_uint(pB[(ks * 8 + 4) * LDB + nt * 8]);
            }
#pragma unroll
            for (int mt = 0; mt < 4; ++mt)
#pragma unroll
                for (int nt = 0; nt < 4; ++nt)
                    mma_tf32(acc[mt][nt], af[mt], bf[nt]);
        }
        buf  = (buf  == 2) ? 0 : buf  + 1;
        bufw = (bufw == 2) ? 0 : bufw + 1;
    }

    // ---- epilogue straight from registers ----
    const float* bp = bias + (size_t)e * ND + n0;
#pragma unroll
    for (int mt = 0; mt < 4; ++mt) {
        const int lr0 = wm * 64 + mt * 16 + (lane >> 2);
#pragma unroll
        for (int h = 0; h < 2; ++h) {
            const int lr = lr0 + h * 8;
            if (m0 + lr >= cnt) continue;
            const int grow = base + m0 + lr;
            const float wt = PH1 ? 0.f : g_wt[g_list[e * NT + m0 + lr]];
#pragma unroll
            for (int nt = 0; nt < 4; ++nt) {
                const int col = wn * 32 + nt * 8 + (lane & 3) * 2;
                float v0 = acc[mt][nt][h * 2 + 0] + bp[col];
                float v1 = acc[mt][nt][h * 2 + 1] + bp[col + 1];
                if (PH1) {
                    v0 = tf32r(0.5f * v0 * (1.f + erff(v0 * 0.70710678118654752f)));
                    v1 = tf32r(0.5f * v1 * (1.f + erff(v1 * 0.70710678118654752f)));
                    float2 o = make_float2(v0, v1);
                    *(float2*)&g_hid[(size_t)grow * NH + n0 + col] = o;
                } else {
                    float2 o = make_float2(wt * v0, wt * v1);
                    *(float2*)&g_tmp[(size_t)grow * CO + n0 + col] = o;
                }
            }
        }
    }
}

// ---------------- combine ----------------------------------------------------
__global__ void k_combine(float* __restrict__ out) {
    int i = blockIdx.x * 256 + threadIdx.x;
    const int tot = NT * CO / 4;
    if (i >= tot) return;
    int t = i / (CO / 4), c = i % (CO / 4);
    int r0 = g_rowof[2 * t], r1 = g_rowof[2 * t + 1];
    const float4* tp = (const float4*)g_tmp;
    float4 u = tp[(size_t)r0 * (CO / 4) + c];
    float4 v = tp[(size_t)r1 * (CO / 4) + c];
    float4 r; r.x = u.x + v.x; r.y = u.y + v.y; r.z = u.z + v.z; r.w = u.w + v.w;
    ((float4*)out)[i] = r;
}

// ---------------- launch -----------------------------------------------------
extern "C" void kernel_launch(void* const* d_in, const int* in_sizes, int n_in,
                              void* d_out, int out_size) {
    const float* x  = (const float*)d_in[0];
    const float* Wg = (const float*)d_in[1];
    const float* bg = (const float*)d_in[2];
    const float* eb = (const float*)d_in[3];
    const float* W1 = (const float*)d_in[4];
    const float* b1 = (const float*)d_in[5];
    const float* W2 = (const float*)d_in[6];
    const float* b2 = (const float*)d_in[7];
    float* out = (float*)d_out;

    cudaFuncSetAttribute(k_mma<CI, NH, true >, cudaFuncAttributeMaxDynamicSharedMemorySize, SMEM_SZ);
    cudaFuncSetAttribute(k_mma<NH, CO, false>, cudaFuncAttributeMaxDynamicSharedMemorySize, SMEM_SZ);

    const int roundw_blocks = (NE * CI * NH / 4 + NE * NH * CO / 4) / 256;  // 2048
    k_zero<<<1, 32>>>();
    k_gate_roundw<<<NT / 8 + roundw_blocks, 256>>>(x, Wg, bg, eb, W1, W2);
    k_sched<<<1, 32>>>();
    k_build<<<NE * NT / 256, 256>>>();

    k_mma<CI, NH, true ><<<dim3(NH / 128, 64, NE), 256, SMEM_SZ>>>(b1);
    k_mma<NH, CO, false><<<dim3(CO / 128, 64, NE), 256, SMEM_SZ>>>(b2);

    k_combine<<<(NT * CO / 4 + 255) / 256, 256>>>(out);
}